// round 7
// baseline (speedup 1.0000x reference)
#include <cuda_runtime.h>
#include <stdint.h>
#include <math.h>

// ============================================================================
// RadialMasking — bit-exact JAX reproduction (fdlibm atan2f, confirmed R4).
//  R7 perf: vectorize the three N-sized passes.
//   k_final : 4xfloat4 per thread (MLP=4), keep mask via nibble array
//   k_finecnt/k_keep: uint4 distk loads, 4 voxels per thread
// ============================================================================

#define NMAX 1600000
#define NB 8

__device__ unsigned int   g_histall[8 + NB * 4][65536];
__device__ __align__(16) unsigned int g_distk[NMAX];   // dist bits | (keep1<<31)
__device__ unsigned char  g_keepnib[NMAX / 4 + 1];     // bit v&3 of byte v>>2
__device__ unsigned int   g_selbits[96];
__device__ unsigned int   g_m[NB];
__device__ int            g_bucket[NB][4];
__device__ int            g_rankin[NB][4];
__device__ float          g_w[NB][4];
__device__ float          g_selval[NB][4];

// ---------------- fdlibm flt-32 atanf / atan2f ------------------------------
__device__ __forceinline__ float fd_atanf(float x) {
    const float atanhi[4] = {4.6364760399e-01f, 7.8539812565e-01f,
                             9.8279368877e-01f, 1.5707962513e+00f};
    const float atanlo[4] = {5.0121582440e-09f, 3.7748947079e-08f,
                             3.4473217170e-08f, 7.5497894159e-08f};
    const float aT0 =  3.3333328366e-01f;
    const float aT1 = -1.9999158382e-01f;
    const float aT2 =  1.4253635705e-01f;
    const float aT3 = -1.0648017377e-01f;
    const float aT4 =  6.1687607318e-02f;
    unsigned ix = __float_as_uint(x);
    unsigned sign = ix >> 31;
    ix &= 0x7fffffffu;
    int id;
    if (ix >= 0x4c800000u) {
        float z = atanhi[3];
        return sign ? -z : z;
    }
    if (ix < 0x3ee00000u) {
        if (ix < 0x39800000u) return x;
        id = -1;
    } else {
        x = fabsf(x);
        if (ix < 0x3f980000u) {
            if (ix < 0x3f300000u) {
                id = 0;
                x = __fdiv_rn(__fsub_rn(__fadd_rn(x, x), 1.0f), __fadd_rn(2.0f, x));
            } else {
                id = 1;
                x = __fdiv_rn(__fsub_rn(x, 1.0f), __fadd_rn(x, 1.0f));
            }
        } else {
            if (ix < 0x401c0000u) {
                id = 2;
                x = __fdiv_rn(__fsub_rn(x, 1.5f), __fadd_rn(1.0f, __fmul_rn(1.5f, x)));
            } else {
                id = 3;
                x = __fdiv_rn(-1.0f, x);
            }
        }
    }
    float z = __fmul_rn(x, x);
    float w = __fmul_rn(z, z);
    float s1 = __fmul_rn(z, __fadd_rn(aT0, __fmul_rn(w, __fadd_rn(aT2, __fmul_rn(w, aT4)))));
    float s2 = __fmul_rn(w, __fadd_rn(aT1, __fmul_rn(w, aT3)));
    if (id < 0)
        return __fsub_rn(x, __fmul_rn(x, __fadd_rn(s1, s2)));
    z = __fsub_rn(atanhi[id],
                  __fsub_rn(__fsub_rn(__fmul_rn(x, __fadd_rn(s1, s2)), atanlo[id]), x));
    return sign ? -z : z;
}

__device__ __forceinline__ float fd_atan2f(float y, float x) {
    const float pi    = 3.1415927410e+00f;
    const float pi_lo = -8.7422776573e-08f;
    const float pio2  = 1.5707963705e+00f;
    unsigned hx = __float_as_uint(x), hy = __float_as_uint(y);
    if (hx == 0x3f800000u) return fd_atanf(y);
    unsigned m = ((hy >> 31) & 1u) | ((hx >> 30) & 2u);
    unsigned ix = hx & 0x7fffffffu, iy = hy & 0x7fffffffu;
    if (iy == 0u) {
        switch (m) {
        case 0: case 1: return y;
        case 2: return pi;
        default: return -pi;
        }
    }
    if (ix == 0u) return (m & 1u) ? -pio2 : pio2;
    if (ix + (26u << 23) < iy) return (m & 1u) ? -pio2 : pio2;
    float z;
    if ((m & 2u) && iy + (26u << 23) < ix)
        z = 0.0f;
    else
        z = fd_atanf(fabsf(__fdiv_rn(y, x)));
    switch (m) {
    case 0: return z;
    case 1: return -z;
    case 2: return __fsub_rn(pi, __fsub_rn(z, pi_lo));
    default: return __fsub_rn(__fsub_rn(z, pi_lo), pi);
    }
}

// ---------------- Threefry-2x32 ----------------------------------------------
__device__ __forceinline__ void tf_round(unsigned& x0, unsigned& x1, int r) {
    x0 += x1;
    x1 = __funnelshift_l(x1, x1, r);
    x1 ^= x0;
}

__device__ __forceinline__ uint2 tf2x32(unsigned k0, unsigned k1, unsigned x0, unsigned x1) {
    unsigned k2 = k0 ^ k1 ^ 0x1BD11BDAu;
    x0 += k0; x1 += k1;
    tf_round(x0, x1, 13); tf_round(x0, x1, 15); tf_round(x0, x1, 26); tf_round(x0, x1, 6);
    x0 += k1; x1 += k2 + 1u;
    tf_round(x0, x1, 17); tf_round(x0, x1, 29); tf_round(x0, x1, 16); tf_round(x0, x1, 24);
    x0 += k2; x1 += k0 + 2u;
    tf_round(x0, x1, 13); tf_round(x0, x1, 15); tf_round(x0, x1, 26); tf_round(x0, x1, 6);
    x0 += k0; x1 += k1 + 3u;
    tf_round(x0, x1, 17); tf_round(x0, x1, 29); tf_round(x0, x1, 16); tf_round(x0, x1, 24);
    x0 += k1; x1 += k2 + 4u;
    tf_round(x0, x1, 13); tf_round(x0, x1, 15); tf_round(x0, x1, 26); tf_round(x0, x1, 6);
    x0 += k2; x1 += k0 + 5u;
    return make_uint2(x0, x1);
}

__device__ __forceinline__ float bits_to_unit(unsigned bits) {
    return __fadd_rn(__uint_as_float((bits >> 9) | 0x3f800000u), -1.0f);
}

__device__ __forceinline__ unsigned warp_iscan(unsigned v, int lane) {
#pragma unroll
    for (int o = 1; o < 32; o <<= 1) {
        unsigned n = __shfl_up_sync(0xffffffffu, v, o);
        if (lane >= o) v += n;
    }
    return v;
}

__device__ __forceinline__ int div_npb(int p, unsigned long long magic) {
    return (int)(((unsigned long long)(unsigned)p * magic) >> 42);
}

// ---------------- k_init ------------------------------------------------------
__global__ void k_init() {
    if (blockIdx.x < 160) {
        uint4* p = (uint4*)&g_histall[0][0];
        unsigned base = blockIdx.x * 4096u + threadIdx.x;
#pragma unroll
        for (int i = 0; i < 4; i++)
            p[base + i * 1024u] = make_uint4(0u, 0u, 0u, 0u);
    } else {
        int t = threadIdx.x;
        if (t < 96) g_selbits[t] = 0u;
        __syncthreads();
        uint2 kg = tf2x32(0u, 42u, 0u, 0u);
        for (int i = t; i < NB * 360; i += 1024) {
            uint2 r = tf2x32(kg.x, kg.y, 0u, (unsigned)i);
            if (bits_to_unit(r.x ^ r.y) < 0.2f)
                atomicOr(&g_selbits[i >> 5], 1u << (i & 31));
        }
    }
}

// ---------------- k_stage1 -----------------------------------------------------
__global__ void k_stage1(const int4* __restrict__ coords, int N) {
    int p = blockIdx.x * blockDim.x + threadIdx.x;
    if (p >= N) return;
    int4 c = coords[p];  // (b, z, y, x)
    float xm = __fadd_rn(__fmul_rn((float)c.w, 0.1f), -70.0f);
    float ym = __fadd_rn(__fmul_rn((float)c.z, 0.1f), -40.0f);
    float th = fd_atan2f(ym, xm);
    float td = __fmul_rn(th, 57.29577951308232f);
    float tm = (td < 0.0f) ? __fadd_rn(td, 360.0f) : td;
    int grp = (int)tm;
    grp = min(max(grp, 0), 359);
    int b = c.x;
    int bitidx = b * 360 + grp;
    unsigned keep1 = (g_selbits[bitidx >> 5] >> (bitidx & 31)) & 1u;
    float d2 = __fadd_rn(__fmul_rn(xm, xm), __fmul_rn(ym, ym));
    float dist = __fsqrt_rn(d2);
    unsigned db = __float_as_uint(dist);
    if (keep1) {
        atomicAdd(&g_histall[b][db >> 16], 1u);
        db |= 0x80000000u;
    }
    g_distk[p] = db;
}

// ---------------- k_coarse -----------------------------------------------------
__global__ void k_coarse() {
    int b = blockIdx.x;
    int t = threadIdx.x, lane = t & 31, warp = t >> 5;
    const unsigned* hist = g_histall[b];
    const uint4* h4 = (const uint4*)hist;
    unsigned psum = 0;
#pragma unroll
    for (int i = 0; i < 16; i++) {
        uint4 q = h4[t * 16 + i];
        psum += q.x + q.y + q.z + q.w;
    }
    unsigned incl = warp_iscan(psum, lane);
    __shared__ unsigned wtot[32], wpre[32];
    __shared__ unsigned s_m;
    __shared__ unsigned s_r[4];
    __shared__ int      s_seg[4];
    __shared__ unsigned s_base[4];
    if (lane == 31) wtot[warp] = incl;
    __syncthreads();
    if (warp == 0) {
        unsigned v = wtot[lane];
        unsigned iv = warp_iscan(v, lane);
        wpre[lane] = iv - v;
        if (lane == 31) s_m = iv;
    }
    __syncthreads();
    unsigned m = s_m;
    if (t == 0) {
        g_m[b] = m;
        float mf  = (float)m;
        float cm1 = __fsub_rn(mf, 1.0f);
        const float qv[2] = {0.33f, 0.67f};
#pragma unroll
        for (int j = 0; j < 2; j++) {
            float qidx = __fmul_rn(qv[j], cm1);
            float lo = floorf(qidx), hi = ceilf(qidx);
            float hw = __fsub_rn(qidx, lo);
            float lw = __fsub_rn(1.0f, hw);
            float loc = fmaxf(0.0f, fminf(lo, cm1));
            float hic = fmaxf(0.0f, fminf(hi, cm1));
            s_r[j * 2]     = (unsigned)(int)loc;
            s_r[j * 2 + 1] = (unsigned)(int)hic;
            g_w[b][j * 2]     = lw;
            g_w[b][j * 2 + 1] = hw;
        }
    }
    __syncthreads();
    if (m != 0) {
        unsigned excl = wpre[warp] + incl - psum;
#pragma unroll
        for (int s = 0; s < 4; s++) {
            unsigned r = s_r[s];
            if (r >= excl && r < excl + psum) { s_seg[s] = t; s_base[s] = excl; }
        }
    }
    __syncthreads();
    if (warp < 4) {
        int s = warp;
        if (m == 0) {
            if (lane == 0) { g_bucket[b][s] = -1; g_rankin[b][s] = 0; }
        } else {
            int seg = s_seg[s];
            unsigned rrem = s_r[s] - s_base[s];
            unsigned a0 = hist[seg * 64 + 2 * lane];
            unsigned a1 = hist[seg * 64 + 2 * lane + 1];
            unsigned pr = a0 + a1;
            unsigned pincl = warp_iscan(pr, lane);
            unsigned pexcl = pincl - pr;
            if (rrem >= pexcl && rrem < pincl) {
                unsigned local = rrem - pexcl;
                int bin; unsigned rk;
                if (local < a0) { bin = seg * 64 + 2 * lane;     rk = local; }
                else            { bin = seg * 64 + 2 * lane + 1; rk = local - a0; }
                g_bucket[b][s] = bin;
                g_rankin[b][s] = (int)rk;
            }
        }
    }
}

// ---------------- k_finecnt: 4 voxels/thread ---------------------------------
__global__ void k_finecnt(int N4, unsigned long long magic) {
    int p4 = blockIdx.x * blockDim.x + threadIdx.x;
    if (p4 >= N4) return;
    uint4 u = ((const uint4*)g_distk)[p4];
    unsigned us[4] = {u.x, u.y, u.z, u.w};
#pragma unroll
    for (int i = 0; i < 4; i++) {
        if (!(us[i] & 0x80000000u)) continue;
        unsigned bits = us[i] & 0x7fffffffu;
        int b = div_npb(p4 * 4 + i, magic);
        int coarse = (int)(bits >> 16);
        unsigned fbin = bits & 0xFFFFu;
#pragma unroll
        for (int s = 0; s < 4; s++)
            if (g_bucket[b][s] == coarse)
                atomicAdd(&g_histall[8 + b * 4 + s][fbin], 1u);
    }
}

// ---------------- k_finescan ---------------------------------------------------
__global__ void k_finescan() {
    int b = blockIdx.x >> 2, s = blockIdx.x & 3;
    int bucket = g_bucket[b][s];
    int t = threadIdx.x, lane = t & 31, warp = t >> 5;
    if (bucket < 0) {
        if (t == 0) g_selval[b][s] = __int_as_float(0x7fc00000);
        return;
    }
    const unsigned* hist = g_histall[8 + b * 4 + s];
    const uint4* h4 = (const uint4*)hist;
    unsigned psum = 0;
#pragma unroll
    for (int i = 0; i < 16; i++) {
        uint4 q = h4[t * 16 + i];
        psum += q.x + q.y + q.z + q.w;
    }
    unsigned incl = warp_iscan(psum, lane);
    __shared__ unsigned wtot[32], wpre[32];
    __shared__ int      s_seg;
    __shared__ unsigned s_base;
    if (lane == 31) wtot[warp] = incl;
    __syncthreads();
    if (warp == 0) {
        unsigned v = wtot[lane];
        unsigned iv = warp_iscan(v, lane);
        wpre[lane] = iv - v;
    }
    __syncthreads();
    unsigned r = (unsigned)g_rankin[b][s];
    unsigned excl = wpre[warp] + incl - psum;
    if (r >= excl && r < excl + psum) { s_seg = t; s_base = excl; }
    __syncthreads();
    if (warp == 0) {
        int seg = s_seg;
        unsigned rrem = r - s_base;
        unsigned a0 = hist[seg * 64 + 2 * lane];
        unsigned a1 = hist[seg * 64 + 2 * lane + 1];
        unsigned pr = a0 + a1;
        unsigned pincl = warp_iscan(pr, lane);
        unsigned pexcl = pincl - pr;
        if (rrem >= pexcl && rrem < pincl) {
            unsigned local = rrem - pexcl;
            int bin = (local < a0) ? (seg * 64 + 2 * lane) : (seg * 64 + 2 * lane + 1);
            g_selval[b][s] = __uint_as_float(((unsigned)bucket << 16) | (unsigned)bin);
        }
    }
}

// ---------------- k_keep: 4 voxels/thread -------------------------------------
__global__ void k_keep(float4* __restrict__ out_keep, int N4, unsigned long long magic) {
    int p4 = blockIdx.x * blockDim.x + threadIdx.x;
    if (p4 >= N4) return;
    uint4 u = ((const uint4*)g_distk)[p4];
    unsigned us[4] = {u.x, u.y, u.z, u.w};
    // all 4 voxels share a batch except across the npb boundary; recompute each
    unsigned nib = 0;
    float kfv[4];
#pragma unroll
    for (int i = 0; i < 4; i++) {
        int p = p4 * 4 + i;
        int b = div_npb(p, magic);
        float dist = __uint_as_float(us[i] & 0x7fffffffu);
        float q1, q2;
        if (g_m[b] == 0) {
            q1 = q2 = __int_as_float(0x7fc00000);
        } else {
            q1 = __fadd_rn(__fmul_rn(g_selval[b][0], g_w[b][0]),
                           __fmul_rn(g_selval[b][1], g_w[b][1]));
            q2 = __fadd_rn(__fmul_rn(g_selval[b][2], g_w[b][2]),
                           __fmul_rn(g_selval[b][3], g_w[b][3]));
        }
        float prob = (dist < q1) ? 0.48f : ((dist < q2) ? 0.8f : 0.95f);
        uint2 kv = tf2x32(0u, 42u, 0u, 1u);
        uint2 r = tf2x32(kv.x, kv.y, 0u, (unsigned)p);
        float uu = bits_to_unit(r.x ^ r.y);
        bool keep = (us[i] >> 31) && (uu >= prob);
        nib |= (keep ? 1u : 0u) << i;
        kfv[i] = keep ? 1.0f : 0.0f;
    }
    g_keepnib[p4] = (unsigned char)nib;
    if (out_keep != nullptr)
        out_keep[p4] = make_float4(kfv[0], kfv[1], kfv[2], kfv[3]);
}

// ---------------- k_final: 4 float4 per thread --------------------------------
__global__ void k_final(const float4* __restrict__ feat, float4* __restrict__ out_feat,
                        long long nthreads) {
    long long idx = (long long)blockIdx.x * blockDim.x + threadIdx.x;
    if (idx >= nthreads) return;
    int v = (int)(idx >> 2);                  // 4 threads per voxel
    unsigned nib = g_keepnib[v >> 2];
    size_t base = (size_t)idx * 4;            // float4 units
    if ((nib >> (v & 3)) & 1u) {
#pragma unroll
        for (int i = 0; i < 4; i++) out_feat[base + i] = feat[base + i];
    } else {
        float4 z = make_float4(0.0f, 0.0f, 0.0f, 0.0f);
#pragma unroll
        for (int i = 0; i < 4; i++) out_feat[base + i] = z;
    }
}

// ---------------- launcher -------------------------------------------------------
extern "C" void kernel_launch(void* const* d_in, const int* in_sizes, int n_in,
                              void* d_out, int out_size) {
    int i_coords = 0, i_feat = 1;
    if (n_in >= 2 && in_sizes[0] > in_sizes[1]) { i_coords = 1; i_feat = 0; }
    const int4*   coords = (const int4*)d_in[i_coords];
    const float4* feat   = (const float4*)d_in[i_feat];
    int N = in_sizes[i_coords] / 4;
    int npb = N / NB;
    unsigned long long magic = (4398046511104ULL / (unsigned long long)npb) + 1ULL;
    int N4 = N / 4;   // N = 8*200000, divisible by 4

    float*  out      = (float*)d_out;
    float4* out_keep = nullptr;
    float4* out_feat = nullptr;
    long long os = (long long)out_size;
    if (os >= (long long)N * 65) {
        out_keep = (float4*)out;
        out_feat = (float4*)(out + N);
    } else if (os >= (long long)N * 64) {
        out_feat = (float4*)out;
    } else {
        out_keep = (float4*)out;
    }

    int nb  = (N + 255) / 256;
    int nb4 = (N4 + 255) / 256;
    k_init<<<161, 1024>>>();
    k_stage1<<<nb, 256>>>(coords, N);
    k_coarse<<<NB, 1024>>>();
    k_finecnt<<<nb4, 256>>>(N4, magic);
    k_finescan<<<NB * 4, 1024>>>();
    k_keep<<<nb4, 256>>>(out_keep, N4, magic);
    if (out_feat != nullptr) {
        long long nthreads = (long long)N * 4;
        k_final<<<(int)((nthreads + 255) / 256), 256>>>(feat, out_feat, nthreads);
    }
}

// round 8
// speedup vs baseline: 1.0023x; 1.0023x over previous
#include <cuda_runtime.h>
#include <stdint.h>
#include <math.h>

// ============================================================================
// RadialMasking — bit-exact JAX reproduction (fdlibm atan2f, confirmed R4).
//  R8 perf: k_keep fused into k_final as an in-block phase (warp0 computes the
//  block's 32 keep flags -> shared bitmask -> 16 warps copy); __ldcs/__stcs
//  streaming hints on the feature stream so distk stays L2-resident.
// ============================================================================

#define NMAX 1600000
#define NB 8

__device__ unsigned int   g_histall[8 + NB * 4][65536];
__device__ __align__(16) unsigned int g_distk[NMAX];   // dist bits | (keep1<<31)
__device__ unsigned int   g_selbits[96];
__device__ unsigned int   g_m[NB];
__device__ int            g_bucket[NB][4];
__device__ int            g_rankin[NB][4];
__device__ float          g_w[NB][4];
__device__ float          g_selval[NB][4];

// ---------------- fdlibm flt-32 atanf / atan2f ------------------------------
__device__ __forceinline__ float fd_atanf(float x) {
    const float atanhi[4] = {4.6364760399e-01f, 7.8539812565e-01f,
                             9.8279368877e-01f, 1.5707962513e+00f};
    const float atanlo[4] = {5.0121582440e-09f, 3.7748947079e-08f,
                             3.4473217170e-08f, 7.5497894159e-08f};
    const float aT0 =  3.3333328366e-01f;
    const float aT1 = -1.9999158382e-01f;
    const float aT2 =  1.4253635705e-01f;
    const float aT3 = -1.0648017377e-01f;
    const float aT4 =  6.1687607318e-02f;
    unsigned ix = __float_as_uint(x);
    unsigned sign = ix >> 31;
    ix &= 0x7fffffffu;
    int id;
    if (ix >= 0x4c800000u) {
        float z = atanhi[3];
        return sign ? -z : z;
    }
    if (ix < 0x3ee00000u) {
        if (ix < 0x39800000u) return x;
        id = -1;
    } else {
        x = fabsf(x);
        if (ix < 0x3f980000u) {
            if (ix < 0x3f300000u) {
                id = 0;
                x = __fdiv_rn(__fsub_rn(__fadd_rn(x, x), 1.0f), __fadd_rn(2.0f, x));
            } else {
                id = 1;
                x = __fdiv_rn(__fsub_rn(x, 1.0f), __fadd_rn(x, 1.0f));
            }
        } else {
            if (ix < 0x401c0000u) {
                id = 2;
                x = __fdiv_rn(__fsub_rn(x, 1.5f), __fadd_rn(1.0f, __fmul_rn(1.5f, x)));
            } else {
                id = 3;
                x = __fdiv_rn(-1.0f, x);
            }
        }
    }
    float z = __fmul_rn(x, x);
    float w = __fmul_rn(z, z);
    float s1 = __fmul_rn(z, __fadd_rn(aT0, __fmul_rn(w, __fadd_rn(aT2, __fmul_rn(w, aT4)))));
    float s2 = __fmul_rn(w, __fadd_rn(aT1, __fmul_rn(w, aT3)));
    if (id < 0)
        return __fsub_rn(x, __fmul_rn(x, __fadd_rn(s1, s2)));
    z = __fsub_rn(atanhi[id],
                  __fsub_rn(__fsub_rn(__fmul_rn(x, __fadd_rn(s1, s2)), atanlo[id]), x));
    return sign ? -z : z;
}

__device__ __forceinline__ float fd_atan2f(float y, float x) {
    const float pi    = 3.1415927410e+00f;
    const float pi_lo = -8.7422776573e-08f;
    const float pio2  = 1.5707963705e+00f;
    unsigned hx = __float_as_uint(x), hy = __float_as_uint(y);
    if (hx == 0x3f800000u) return fd_atanf(y);
    unsigned m = ((hy >> 31) & 1u) | ((hx >> 30) & 2u);
    unsigned ix = hx & 0x7fffffffu, iy = hy & 0x7fffffffu;
    if (iy == 0u) {
        switch (m) {
        case 0: case 1: return y;
        case 2: return pi;
        default: return -pi;
        }
    }
    if (ix == 0u) return (m & 1u) ? -pio2 : pio2;
    if (ix + (26u << 23) < iy) return (m & 1u) ? -pio2 : pio2;
    float z;
    if ((m & 2u) && iy + (26u << 23) < ix)
        z = 0.0f;
    else
        z = fd_atanf(fabsf(__fdiv_rn(y, x)));
    switch (m) {
    case 0: return z;
    case 1: return -z;
    case 2: return __fsub_rn(pi, __fsub_rn(z, pi_lo));
    default: return __fsub_rn(__fsub_rn(z, pi_lo), pi);
    }
}

// ---------------- Threefry-2x32 ----------------------------------------------
__device__ __forceinline__ void tf_round(unsigned& x0, unsigned& x1, int r) {
    x0 += x1;
    x1 = __funnelshift_l(x1, x1, r);
    x1 ^= x0;
}

__device__ __forceinline__ uint2 tf2x32(unsigned k0, unsigned k1, unsigned x0, unsigned x1) {
    unsigned k2 = k0 ^ k1 ^ 0x1BD11BDAu;
    x0 += k0; x1 += k1;
    tf_round(x0, x1, 13); tf_round(x0, x1, 15); tf_round(x0, x1, 26); tf_round(x0, x1, 6);
    x0 += k1; x1 += k2 + 1u;
    tf_round(x0, x1, 17); tf_round(x0, x1, 29); tf_round(x0, x1, 16); tf_round(x0, x1, 24);
    x0 += k2; x1 += k0 + 2u;
    tf_round(x0, x1, 13); tf_round(x0, x1, 15); tf_round(x0, x1, 26); tf_round(x0, x1, 6);
    x0 += k0; x1 += k1 + 3u;
    tf_round(x0, x1, 17); tf_round(x0, x1, 29); tf_round(x0, x1, 16); tf_round(x0, x1, 24);
    x0 += k1; x1 += k2 + 4u;
    tf_round(x0, x1, 13); tf_round(x0, x1, 15); tf_round(x0, x1, 26); tf_round(x0, x1, 6);
    x0 += k2; x1 += k0 + 5u;
    return make_uint2(x0, x1);
}

__device__ __forceinline__ float bits_to_unit(unsigned bits) {
    return __fadd_rn(__uint_as_float((bits >> 9) | 0x3f800000u), -1.0f);
}

__device__ __forceinline__ unsigned warp_iscan(unsigned v, int lane) {
#pragma unroll
    for (int o = 1; o < 32; o <<= 1) {
        unsigned n = __shfl_up_sync(0xffffffffu, v, o);
        if (lane >= o) v += n;
    }
    return v;
}

__device__ __forceinline__ int div_npb(int p, unsigned long long magic) {
    return (int)(((unsigned long long)(unsigned)p * magic) >> 42);
}

// ---------------- k_init ------------------------------------------------------
__global__ void k_init() {
    if (blockIdx.x < 160) {
        uint4* p = (uint4*)&g_histall[0][0];
        unsigned base = blockIdx.x * 4096u + threadIdx.x;
#pragma unroll
        for (int i = 0; i < 4; i++)
            p[base + i * 1024u] = make_uint4(0u, 0u, 0u, 0u);
    } else {
        int t = threadIdx.x;
        if (t < 96) g_selbits[t] = 0u;
        __syncthreads();
        uint2 kg = tf2x32(0u, 42u, 0u, 0u);
        for (int i = t; i < NB * 360; i += 1024) {
            uint2 r = tf2x32(kg.x, kg.y, 0u, (unsigned)i);
            if (bits_to_unit(r.x ^ r.y) < 0.2f)
                atomicOr(&g_selbits[i >> 5], 1u << (i & 31));
        }
    }
}

// ---------------- k_stage1 -----------------------------------------------------
__global__ void k_stage1(const int4* __restrict__ coords, int N) {
    int p = blockIdx.x * blockDim.x + threadIdx.x;
    if (p >= N) return;
    int4 c = coords[p];  // (b, z, y, x)
    float xm = __fadd_rn(__fmul_rn((float)c.w, 0.1f), -70.0f);
    float ym = __fadd_rn(__fmul_rn((float)c.z, 0.1f), -40.0f);
    float th = fd_atan2f(ym, xm);
    float td = __fmul_rn(th, 57.29577951308232f);
    float tm = (td < 0.0f) ? __fadd_rn(td, 360.0f) : td;
    int grp = (int)tm;
    grp = min(max(grp, 0), 359);
    int b = c.x;
    int bitidx = b * 360 + grp;
    unsigned keep1 = (g_selbits[bitidx >> 5] >> (bitidx & 31)) & 1u;
    float d2 = __fadd_rn(__fmul_rn(xm, xm), __fmul_rn(ym, ym));
    float dist = __fsqrt_rn(d2);
    unsigned db = __float_as_uint(dist);
    if (keep1) {
        atomicAdd(&g_histall[b][db >> 16], 1u);
        db |= 0x80000000u;
    }
    g_distk[p] = db;
}

// ---------------- k_coarse -----------------------------------------------------
__global__ void k_coarse() {
    int b = blockIdx.x;
    int t = threadIdx.x, lane = t & 31, warp = t >> 5;
    const unsigned* hist = g_histall[b];
    const uint4* h4 = (const uint4*)hist;
    unsigned psum = 0;
#pragma unroll
    for (int i = 0; i < 16; i++) {
        uint4 q = h4[t * 16 + i];
        psum += q.x + q.y + q.z + q.w;
    }
    unsigned incl = warp_iscan(psum, lane);
    __shared__ unsigned wtot[32], wpre[32];
    __shared__ unsigned s_m;
    __shared__ unsigned s_r[4];
    __shared__ int      s_seg[4];
    __shared__ unsigned s_base[4];
    if (lane == 31) wtot[warp] = incl;
    __syncthreads();
    if (warp == 0) {
        unsigned v = wtot[lane];
        unsigned iv = warp_iscan(v, lane);
        wpre[lane] = iv - v;
        if (lane == 31) s_m = iv;
    }
    __syncthreads();
    unsigned m = s_m;
    if (t == 0) {
        g_m[b] = m;
        float mf  = (float)m;
        float cm1 = __fsub_rn(mf, 1.0f);
        const float qv[2] = {0.33f, 0.67f};
#pragma unroll
        for (int j = 0; j < 2; j++) {
            float qidx = __fmul_rn(qv[j], cm1);
            float lo = floorf(qidx), hi = ceilf(qidx);
            float hw = __fsub_rn(qidx, lo);
            float lw = __fsub_rn(1.0f, hw);
            float loc = fmaxf(0.0f, fminf(lo, cm1));
            float hic = fmaxf(0.0f, fminf(hi, cm1));
            s_r[j * 2]     = (unsigned)(int)loc;
            s_r[j * 2 + 1] = (unsigned)(int)hic;
            g_w[b][j * 2]     = lw;
            g_w[b][j * 2 + 1] = hw;
        }
    }
    __syncthreads();
    if (m != 0) {
        unsigned excl = wpre[warp] + incl - psum;
#pragma unroll
        for (int s = 0; s < 4; s++) {
            unsigned r = s_r[s];
            if (r >= excl && r < excl + psum) { s_seg[s] = t; s_base[s] = excl; }
        }
    }
    __syncthreads();
    if (warp < 4) {
        int s = warp;
        if (m == 0) {
            if (lane == 0) { g_bucket[b][s] = -1; g_rankin[b][s] = 0; }
        } else {
            int seg = s_seg[s];
            unsigned rrem = s_r[s] - s_base[s];
            unsigned a0 = hist[seg * 64 + 2 * lane];
            unsigned a1 = hist[seg * 64 + 2 * lane + 1];
            unsigned pr = a0 + a1;
            unsigned pincl = warp_iscan(pr, lane);
            unsigned pexcl = pincl - pr;
            if (rrem >= pexcl && rrem < pincl) {
                unsigned local = rrem - pexcl;
                int bin; unsigned rk;
                if (local < a0) { bin = seg * 64 + 2 * lane;     rk = local; }
                else            { bin = seg * 64 + 2 * lane + 1; rk = local - a0; }
                g_bucket[b][s] = bin;
                g_rankin[b][s] = (int)rk;
            }
        }
    }
}

// ---------------- k_finecnt: 4 voxels/thread ---------------------------------
__global__ void k_finecnt(int N4, unsigned long long magic) {
    int p4 = blockIdx.x * blockDim.x + threadIdx.x;
    if (p4 >= N4) return;
    uint4 u = ((const uint4*)g_distk)[p4];
    unsigned us[4] = {u.x, u.y, u.z, u.w};
#pragma unroll
    for (int i = 0; i < 4; i++) {
        if (!(us[i] & 0x80000000u)) continue;
        unsigned bits = us[i] & 0x7fffffffu;
        int b = div_npb(p4 * 4 + i, magic);
        int coarse = (int)(bits >> 16);
        unsigned fbin = bits & 0xFFFFu;
#pragma unroll
        for (int s = 0; s < 4; s++)
            if (g_bucket[b][s] == coarse)
                atomicAdd(&g_histall[8 + b * 4 + s][fbin], 1u);
    }
}

// ---------------- k_finescan ---------------------------------------------------
__global__ void k_finescan() {
    int b = blockIdx.x >> 2, s = blockIdx.x & 3;
    int bucket = g_bucket[b][s];
    int t = threadIdx.x, lane = t & 31, warp = t >> 5;
    if (bucket < 0) {
        if (t == 0) g_selval[b][s] = __int_as_float(0x7fc00000);
        return;
    }
    const unsigned* hist = g_histall[8 + b * 4 + s];
    const uint4* h4 = (const uint4*)hist;
    unsigned psum = 0;
#pragma unroll
    for (int i = 0; i < 16; i++) {
        uint4 q = h4[t * 16 + i];
        psum += q.x + q.y + q.z + q.w;
    }
    unsigned incl = warp_iscan(psum, lane);
    __shared__ unsigned wtot[32], wpre[32];
    __shared__ int      s_seg;
    __shared__ unsigned s_base;
    if (lane == 31) wtot[warp] = incl;
    __syncthreads();
    if (warp == 0) {
        unsigned v = wtot[lane];
        unsigned iv = warp_iscan(v, lane);
        wpre[lane] = iv - v;
    }
    __syncthreads();
    unsigned r = (unsigned)g_rankin[b][s];
    unsigned excl = wpre[warp] + incl - psum;
    if (r >= excl && r < excl + psum) { s_seg = t; s_base = excl; }
    __syncthreads();
    if (warp == 0) {
        int seg = s_seg;
        unsigned rrem = r - s_base;
        unsigned a0 = hist[seg * 64 + 2 * lane];
        unsigned a1 = hist[seg * 64 + 2 * lane + 1];
        unsigned pr = a0 + a1;
        unsigned pincl = warp_iscan(pr, lane);
        unsigned pexcl = pincl - pr;
        if (rrem >= pexcl && rrem < pincl) {
            unsigned local = rrem - pexcl;
            int bin = (local < a0) ? (seg * 64 + 2 * lane) : (seg * 64 + 2 * lane + 1);
            g_selval[b][s] = __uint_as_float(((unsigned)bucket << 16) | (unsigned)bin);
        }
    }
}

// ---------------- k_final: fused keep + copy ----------------------------------
// Block = 512 threads = 32 voxels. Phase 1: warp 0 (32 active lanes, one
// Threefry each) computes keep for the block's 32 voxels, writes out_keep,
// publishes bitmask to shared. Phase 2: 16 warps copy/zero (16 threads/voxel,
// coalesced 512B per warp-instruction), streaming cache hints.
__global__ void k_final(const float4* __restrict__ feat, float* __restrict__ out_keep,
                        float4* __restrict__ out_feat, int N, unsigned long long magic) {
    __shared__ unsigned s_keep;
    int t = threadIdx.x;
    int vbase = blockIdx.x * 32;
    if (t < 32) {
        int p = vbase + t;
        bool keep = false;
        if (p < N) {
            unsigned u = g_distk[p];
            float dist = __uint_as_float(u & 0x7fffffffu);
            int b = div_npb(p, magic);
            float q1, q2;
            if (g_m[b] == 0) {
                q1 = q2 = __int_as_float(0x7fc00000);
            } else {
                q1 = __fadd_rn(__fmul_rn(g_selval[b][0], g_w[b][0]),
                               __fmul_rn(g_selval[b][1], g_w[b][1]));
                q2 = __fadd_rn(__fmul_rn(g_selval[b][2], g_w[b][2]),
                               __fmul_rn(g_selval[b][3], g_w[b][3]));
            }
            float prob = (dist < q1) ? 0.48f : ((dist < q2) ? 0.8f : 0.95f);
            uint2 kv = tf2x32(0u, 42u, 0u, 1u);
            uint2 r = tf2x32(kv.x, kv.y, 0u, (unsigned)p);
            float uu = bits_to_unit(r.x ^ r.y);
            keep = (u >> 31) && (uu >= prob);
            if (out_keep != nullptr) out_keep[p] = keep ? 1.0f : 0.0f;
        }
        unsigned bal = __ballot_sync(0xffffffffu, keep);
        if (t == 0) s_keep = bal;
    }
    __syncthreads();
    if (out_feat == nullptr) return;
    int vloc = t >> 4;                 // 0..31
    int v = vbase + vloc;
    if (v >= N) return;
    int lane16 = t & 15;
    size_t off = (size_t)v * 16 + lane16;
    if ((s_keep >> vloc) & 1u) {
        __stcs(&out_feat[off], __ldcs(&feat[off]));
    } else {
        __stcs(&out_feat[off], make_float4(0.0f, 0.0f, 0.0f, 0.0f));
    }
}

// ---------------- launcher -------------------------------------------------------
extern "C" void kernel_launch(void* const* d_in, const int* in_sizes, int n_in,
                              void* d_out, int out_size) {
    int i_coords = 0, i_feat = 1;
    if (n_in >= 2 && in_sizes[0] > in_sizes[1]) { i_coords = 1; i_feat = 0; }
    const int4*   coords = (const int4*)d_in[i_coords];
    const float4* feat   = (const float4*)d_in[i_feat];
    int N = in_sizes[i_coords] / 4;
    int npb = N / NB;
    unsigned long long magic = (4398046511104ULL / (unsigned long long)npb) + 1ULL;
    int N4 = N / 4;

    float*  out      = (float*)d_out;
    float*  out_keep = nullptr;
    float4* out_feat = nullptr;
    long long os = (long long)out_size;
    if (os >= (long long)N * 65) {
        out_keep = out;
        out_feat = (float4*)(out + N);
    } else if (os >= (long long)N * 64) {
        out_feat = (float4*)out;
    } else {
        out_keep = out;
    }

    int nb  = (N + 255) / 256;
    int nb4 = (N4 + 255) / 256;
    k_init<<<161, 1024>>>();
    k_stage1<<<nb, 256>>>(coords, N);
    k_coarse<<<NB, 1024>>>();
    k_finecnt<<<nb4, 256>>>(N4, magic);
    k_finescan<<<NB * 4, 1024>>>();
    k_final<<<(N + 31) / 32, 512>>>(feat, out_keep, out_feat, N, magic);
}

// round 9
// speedup vs baseline: 1.0257x; 1.0234x over previous
#include <cuda_runtime.h>
#include <stdint.h>
#include <math.h>

// ============================================================================
// RadialMasking — bit-exact JAX reproduction (fdlibm atan2f, confirmed R4).
//  R8 perf: k_keep fused into k_final as an in-block phase (warp0 computes the
//  block's 32 keep flags -> shared bitmask -> 16 warps copy); __ldcs/__stcs
//  streaming hints on the feature stream so distk stays L2-resident.
// ============================================================================

#define NMAX 1600000
#define NB 8

__device__ unsigned int   g_histall[8 + NB * 4][65536];
__device__ __align__(16) unsigned int g_distk[NMAX];   // dist bits | (keep1<<31)
__device__ unsigned int   g_selbits[96];
__device__ unsigned int   g_m[NB];
__device__ int            g_bucket[NB][4];
__device__ int            g_rankin[NB][4];
__device__ float          g_w[NB][4];
__device__ float          g_selval[NB][4];

// ---------------- fdlibm flt-32 atanf / atan2f ------------------------------
__device__ __forceinline__ float fd_atanf(float x) {
    const float atanhi[4] = {4.6364760399e-01f, 7.8539812565e-01f,
                             9.8279368877e-01f, 1.5707962513e+00f};
    const float atanlo[4] = {5.0121582440e-09f, 3.7748947079e-08f,
                             3.4473217170e-08f, 7.5497894159e-08f};
    const float aT0 =  3.3333328366e-01f;
    const float aT1 = -1.9999158382e-01f;
    const float aT2 =  1.4253635705e-01f;
    const float aT3 = -1.0648017377e-01f;
    const float aT4 =  6.1687607318e-02f;
    unsigned ix = __float_as_uint(x);
    unsigned sign = ix >> 31;
    ix &= 0x7fffffffu;
    int id;
    if (ix >= 0x4c800000u) {
        float z = atanhi[3];
        return sign ? -z : z;
    }
    if (ix < 0x3ee00000u) {
        if (ix < 0x39800000u) return x;
        id = -1;
    } else {
        x = fabsf(x);
        if (ix < 0x3f980000u) {
            if (ix < 0x3f300000u) {
                id = 0;
                x = __fdiv_rn(__fsub_rn(__fadd_rn(x, x), 1.0f), __fadd_rn(2.0f, x));
            } else {
                id = 1;
                x = __fdiv_rn(__fsub_rn(x, 1.0f), __fadd_rn(x, 1.0f));
            }
        } else {
            if (ix < 0x401c0000u) {
                id = 2;
                x = __fdiv_rn(__fsub_rn(x, 1.5f), __fadd_rn(1.0f, __fmul_rn(1.5f, x)));
            } else {
                id = 3;
                x = __fdiv_rn(-1.0f, x);
            }
        }
    }
    float z = __fmul_rn(x, x);
    float w = __fmul_rn(z, z);
    float s1 = __fmul_rn(z, __fadd_rn(aT0, __fmul_rn(w, __fadd_rn(aT2, __fmul_rn(w, aT4)))));
    float s2 = __fmul_rn(w, __fadd_rn(aT1, __fmul_rn(w, aT3)));
    if (id < 0)
        return __fsub_rn(x, __fmul_rn(x, __fadd_rn(s1, s2)));
    z = __fsub_rn(atanhi[id],
                  __fsub_rn(__fsub_rn(__fmul_rn(x, __fadd_rn(s1, s2)), atanlo[id]), x));
    return sign ? -z : z;
}

__device__ __forceinline__ float fd_atan2f(float y, float x) {
    const float pi    = 3.1415927410e+00f;
    const float pi_lo = -8.7422776573e-08f;
    const float pio2  = 1.5707963705e+00f;
    unsigned hx = __float_as_uint(x), hy = __float_as_uint(y);
    if (hx == 0x3f800000u) return fd_atanf(y);
    unsigned m = ((hy >> 31) & 1u) | ((hx >> 30) & 2u);
    unsigned ix = hx & 0x7fffffffu, iy = hy & 0x7fffffffu;
    if (iy == 0u) {
        switch (m) {
        case 0: case 1: return y;
        case 2: return pi;
        default: return -pi;
        }
    }
    if (ix == 0u) return (m & 1u) ? -pio2 : pio2;
    if (ix + (26u << 23) < iy) return (m & 1u) ? -pio2 : pio2;
    float z;
    if ((m & 2u) && iy + (26u << 23) < ix)
        z = 0.0f;
    else
        z = fd_atanf(fabsf(__fdiv_rn(y, x)));
    switch (m) {
    case 0: return z;
    case 1: return -z;
    case 2: return __fsub_rn(pi, __fsub_rn(z, pi_lo));
    default: return __fsub_rn(__fsub_rn(z, pi_lo), pi);
    }
}

// ---------------- Threefry-2x32 ----------------------------------------------
__device__ __forceinline__ void tf_round(unsigned& x0, unsigned& x1, int r) {
    x0 += x1;
    x1 = __funnelshift_l(x1, x1, r);
    x1 ^= x0;
}

__device__ __forceinline__ uint2 tf2x32(unsigned k0, unsigned k1, unsigned x0, unsigned x1) {
    unsigned k2 = k0 ^ k1 ^ 0x1BD11BDAu;
    x0 += k0; x1 += k1;
    tf_round(x0, x1, 13); tf_round(x0, x1, 15); tf_round(x0, x1, 26); tf_round(x0, x1, 6);
    x0 += k1; x1 += k2 + 1u;
    tf_round(x0, x1, 17); tf_round(x0, x1, 29); tf_round(x0, x1, 16); tf_round(x0, x1, 24);
    x0 += k2; x1 += k0 + 2u;
    tf_round(x0, x1, 13); tf_round(x0, x1, 15); tf_round(x0, x1, 26); tf_round(x0, x1, 6);
    x0 += k0; x1 += k1 + 3u;
    tf_round(x0, x1, 17); tf_round(x0, x1, 29); tf_round(x0, x1, 16); tf_round(x0, x1, 24);
    x0 += k1; x1 += k2 + 4u;
    tf_round(x0, x1, 13); tf_round(x0, x1, 15); tf_round(x0, x1, 26); tf_round(x0, x1, 6);
    x0 += k2; x1 += k0 + 5u;
    return make_uint2(x0, x1);
}

__device__ __forceinline__ float bits_to_unit(unsigned bits) {
    return __fadd_rn(__uint_as_float((bits >> 9) | 0x3f800000u), -1.0f);
}

__device__ __forceinline__ unsigned warp_iscan(unsigned v, int lane) {
#pragma unroll
    for (int o = 1; o < 32; o <<= 1) {
        unsigned n = __shfl_up_sync(0xffffffffu, v, o);
        if (lane >= o) v += n;
    }
    return v;
}

__device__ __forceinline__ int div_npb(int p, unsigned long long magic) {
    return (int)(((unsigned long long)(unsigned)p * magic) >> 42);
}

// ---------------- k_init ------------------------------------------------------
__global__ void k_init() {
    if (blockIdx.x < 160) {
        uint4* p = (uint4*)&g_histall[0][0];
        unsigned base = blockIdx.x * 4096u + threadIdx.x;
#pragma unroll
        for (int i = 0; i < 4; i++)
            p[base + i * 1024u] = make_uint4(0u, 0u, 0u, 0u);
    } else {
        int t = threadIdx.x;
        if (t < 96) g_selbits[t] = 0u;
        __syncthreads();
        uint2 kg = tf2x32(0u, 42u, 0u, 0u);
        for (int i = t; i < NB * 360; i += 1024) {
            uint2 r = tf2x32(kg.x, kg.y, 0u, (unsigned)i);
            if (bits_to_unit(r.x ^ r.y) < 0.2f)
                atomicOr(&g_selbits[i >> 5], 1u << (i & 31));
        }
    }
}

// ---------------- k_stage1 -----------------------------------------------------
__global__ void k_stage1(const int4* __restrict__ coords, int N) {
    int p = blockIdx.x * blockDim.x + threadIdx.x;
    if (p >= N) return;
    int4 c = coords[p];  // (b, z, y, x)
    float xm = __fadd_rn(__fmul_rn((float)c.w, 0.1f), -70.0f);
    float ym = __fadd_rn(__fmul_rn((float)c.z, 0.1f), -40.0f);
    float th = fd_atan2f(ym, xm);
    float td = __fmul_rn(th, 57.29577951308232f);
    float tm = (td < 0.0f) ? __fadd_rn(td, 360.0f) : td;
    int grp = (int)tm;
    grp = min(max(grp, 0), 359);
    int b = c.x;
    int bitidx = b * 360 + grp;
    unsigned keep1 = (g_selbits[bitidx >> 5] >> (bitidx & 31)) & 1u;
    float d2 = __fadd_rn(__fmul_rn(xm, xm), __fmul_rn(ym, ym));
    float dist = __fsqrt_rn(d2);
    unsigned db = __float_as_uint(dist);
    if (keep1) {
        atomicAdd(&g_histall[b][db >> 16], 1u);
        db |= 0x80000000u;
    }
    g_distk[p] = db;
}

// ---------------- k_coarse -----------------------------------------------------
__global__ void k_coarse() {
    int b = blockIdx.x;
    int t = threadIdx.x, lane = t & 31, warp = t >> 5;
    const unsigned* hist = g_histall[b];
    const uint4* h4 = (const uint4*)hist;
    unsigned psum = 0;
#pragma unroll
    for (int i = 0; i < 16; i++) {
        uint4 q = h4[t * 16 + i];
        psum += q.x + q.y + q.z + q.w;
    }
    unsigned incl = warp_iscan(psum, lane);
    __shared__ unsigned wtot[32], wpre[32];
    __shared__ unsigned s_m;
    __shared__ unsigned s_r[4];
    __shared__ int      s_seg[4];
    __shared__ unsigned s_base[4];
    if (lane == 31) wtot[warp] = incl;
    __syncthreads();
    if (warp == 0) {
        unsigned v = wtot[lane];
        unsigned iv = warp_iscan(v, lane);
        wpre[lane] = iv - v;
        if (lane == 31) s_m = iv;
    }
    __syncthreads();
    unsigned m = s_m;
    if (t == 0) {
        g_m[b] = m;
        float mf  = (float)m;
        float cm1 = __fsub_rn(mf, 1.0f);
        const float qv[2] = {0.33f, 0.67f};
#pragma unroll
        for (int j = 0; j < 2; j++) {
            float qidx = __fmul_rn(qv[j], cm1);
            float lo = floorf(qidx), hi = ceilf(qidx);
            float hw = __fsub_rn(qidx, lo);
            float lw = __fsub_rn(1.0f, hw);
            float loc = fmaxf(0.0f, fminf(lo, cm1));
            float hic = fmaxf(0.0f, fminf(hi, cm1));
            s_r[j * 2]     = (unsigned)(int)loc;
            s_r[j * 2 + 1] = (unsigned)(int)hic;
            g_w[b][j * 2]     = lw;
            g_w[b][j * 2 + 1] = hw;
        }
    }
    __syncthreads();
    if (m != 0) {
        unsigned excl = wpre[warp] + incl - psum;
#pragma unroll
        for (int s = 0; s < 4; s++) {
            unsigned r = s_r[s];
            if (r >= excl && r < excl + psum) { s_seg[s] = t; s_base[s] = excl; }
        }
    }
    __syncthreads();
    if (warp < 4) {
        int s = warp;
        if (m == 0) {
            if (lane == 0) { g_bucket[b][s] = -1; g_rankin[b][s] = 0; }
        } else {
            int seg = s_seg[s];
            unsigned rrem = s_r[s] - s_base[s];
            unsigned a0 = hist[seg * 64 + 2 * lane];
            unsigned a1 = hist[seg * 64 + 2 * lane + 1];
            unsigned pr = a0 + a1;
            unsigned pincl = warp_iscan(pr, lane);
            unsigned pexcl = pincl - pr;
            if (rrem >= pexcl && rrem < pincl) {
                unsigned local = rrem - pexcl;
                int bin; unsigned rk;
                if (local < a0) { bin = seg * 64 + 2 * lane;     rk = local; }
                else            { bin = seg * 64 + 2 * lane + 1; rk = local - a0; }
                g_bucket[b][s] = bin;
                g_rankin[b][s] = (int)rk;
            }
        }
    }
}

// ---------------- k_finecnt: 4 voxels/thread ---------------------------------
__global__ void k_finecnt(int N4, unsigned long long magic) {
    int p4 = blockIdx.x * blockDim.x + threadIdx.x;
    if (p4 >= N4) return;
    uint4 u = ((const uint4*)g_distk)[p4];
    unsigned us[4] = {u.x, u.y, u.z, u.w};
#pragma unroll
    for (int i = 0; i < 4; i++) {
        if (!(us[i] & 0x80000000u)) continue;
        unsigned bits = us[i] & 0x7fffffffu;
        int b = div_npb(p4 * 4 + i, magic);
        int coarse = (int)(bits >> 16);
        unsigned fbin = bits & 0xFFFFu;
#pragma unroll
        for (int s = 0; s < 4; s++)
            if (g_bucket[b][s] == coarse)
                atomicAdd(&g_histall[8 + b * 4 + s][fbin], 1u);
    }
}

// ---------------- k_finescan ---------------------------------------------------
__global__ void k_finescan() {
    int b = blockIdx.x >> 2, s = blockIdx.x & 3;
    int bucket = g_bucket[b][s];
    int t = threadIdx.x, lane = t & 31, warp = t >> 5;
    if (bucket < 0) {
        if (t == 0) g_selval[b][s] = __int_as_float(0x7fc00000);
        return;
    }
    const unsigned* hist = g_histall[8 + b * 4 + s];
    const uint4* h4 = (const uint4*)hist;
    unsigned psum = 0;
#pragma unroll
    for (int i = 0; i < 16; i++) {
        uint4 q = h4[t * 16 + i];
        psum += q.x + q.y + q.z + q.w;
    }
    unsigned incl = warp_iscan(psum, lane);
    __shared__ unsigned wtot[32], wpre[32];
    __shared__ int      s_seg;
    __shared__ unsigned s_base;
    if (lane == 31) wtot[warp] = incl;
    __syncthreads();
    if (warp == 0) {
        unsigned v = wtot[lane];
        unsigned iv = warp_iscan(v, lane);
        wpre[lane] = iv - v;
    }
    __syncthreads();
    unsigned r = (unsigned)g_rankin[b][s];
    unsigned excl = wpre[warp] + incl - psum;
    if (r >= excl && r < excl + psum) { s_seg = t; s_base = excl; }
    __syncthreads();
    if (warp == 0) {
        int seg = s_seg;
        unsigned rrem = r - s_base;
        unsigned a0 = hist[seg * 64 + 2 * lane];
        unsigned a1 = hist[seg * 64 + 2 * lane + 1];
        unsigned pr = a0 + a1;
        unsigned pincl = warp_iscan(pr, lane);
        unsigned pexcl = pincl - pr;
        if (rrem >= pexcl && rrem < pincl) {
            unsigned local = rrem - pexcl;
            int bin = (local < a0) ? (seg * 64 + 2 * lane) : (seg * 64 + 2 * lane + 1);
            g_selval[b][s] = __uint_as_float(((unsigned)bucket << 16) | (unsigned)bin);
        }
    }
}

// ---------------- k_final: fused keep + copy ----------------------------------
// Block = 512 threads = 32 voxels. Phase 1: warp 0 (32 active lanes, one
// Threefry each) computes keep for the block's 32 voxels, writes out_keep,
// publishes bitmask to shared. Phase 2: 16 warps copy/zero (16 threads/voxel,
// coalesced 512B per warp-instruction), streaming cache hints.
__global__ void k_final(const float4* __restrict__ feat, float* __restrict__ out_keep,
                        float4* __restrict__ out_feat, int N, unsigned long long magic) {
    __shared__ unsigned s_keep;
    int t = threadIdx.x;
    int vbase = blockIdx.x * 32;
    if (t < 32) {
        int p = vbase + t;
        bool keep = false;
        if (p < N) {
            unsigned u = g_distk[p];
            float dist = __uint_as_float(u & 0x7fffffffu);
            int b = div_npb(p, magic);
            float q1, q2;
            if (g_m[b] == 0) {
                q1 = q2 = __int_as_float(0x7fc00000);
            } else {
                q1 = __fadd_rn(__fmul_rn(g_selval[b][0], g_w[b][0]),
                               __fmul_rn(g_selval[b][1], g_w[b][1]));
                q2 = __fadd_rn(__fmul_rn(g_selval[b][2], g_w[b][2]),
                               __fmul_rn(g_selval[b][3], g_w[b][3]));
            }
            float prob = (dist < q1) ? 0.48f : ((dist < q2) ? 0.8f : 0.95f);
            uint2 kv = tf2x32(0u, 42u, 0u, 1u);
            uint2 r = tf2x32(kv.x, kv.y, 0u, (unsigned)p);
            float uu = bits_to_unit(r.x ^ r.y);
            keep = (u >> 31) && (uu >= prob);
            if (out_keep != nullptr) out_keep[p] = keep ? 1.0f : 0.0f;
        }
        unsigned bal = __ballot_sync(0xffffffffu, keep);
        if (t == 0) s_keep = bal;
    }
    __syncthreads();
    if (out_feat == nullptr) return;
    int vloc = t >> 4;                 // 0..31
    int v = vbase + vloc;
    if (v >= N) return;
    int lane16 = t & 15;
    size_t off = (size_t)v * 16 + lane16;
    if ((s_keep >> vloc) & 1u) {
        __stcs(&out_feat[off], __ldcs(&feat[off]));
    } else {
        __stcs(&out_feat[off], make_float4(0.0f, 0.0f, 0.0f, 0.0f));
    }
}

// ---------------- launcher -------------------------------------------------------
extern "C" void kernel_launch(void* const* d_in, const int* in_sizes, int n_in,
                              void* d_out, int out_size) {
    int i_coords = 0, i_feat = 1;
    if (n_in >= 2 && in_sizes[0] > in_sizes[1]) { i_coords = 1; i_feat = 0; }
    const int4*   coords = (const int4*)d_in[i_coords];
    const float4* feat   = (const float4*)d_in[i_feat];
    int N = in_sizes[i_coords] / 4;
    int npb = N / NB;
    unsigned long long magic = (4398046511104ULL / (unsigned long long)npb) + 1ULL;
    int N4 = N / 4;

    float*  out      = (float*)d_out;
    float*  out_keep = nullptr;
    float4* out_feat = nullptr;
    long long os = (long long)out_size;
    if (os >= (long long)N * 65) {
        out_keep = out;
        out_feat = (float4*)(out + N);
    } else if (os >= (long long)N * 64) {
        out_feat = (float4*)out;
    } else {
        out_keep = out;
    }

    int nb  = (N + 255) / 256;
    int nb4 = (N4 + 255) / 256;
    k_init<<<161, 1024>>>();
    k_stage1<<<nb, 256>>>(coords, N);
    k_coarse<<<NB, 1024>>>();
    k_finecnt<<<nb4, 256>>>(N4, magic);
    k_finescan<<<NB * 4, 1024>>>();
    k_final<<<(N + 31) / 32, 512>>>(feat, out_keep, out_feat, N, magic);
}

// round 10
// speedup vs baseline: 1.0816x; 1.0545x over previous
#include <cuda_runtime.h>
#include <stdint.h>
#include <math.h>

// ============================================================================
// RadialMasking — bit-exact JAX reproduction (fdlibm atan2f, confirmed R4).
//  R10 perf: branchless fdlibm atanf (one div, predicated interval selects --
//  removes 4-way warp divergence in stage1); atan2 tail via selects;
//  k_finecnt caches g_bucket in shared.
// ============================================================================

#define NMAX 1600000
#define NB 8

__device__ unsigned int   g_histall[8 + NB * 4][65536];
__device__ __align__(16) unsigned int g_distk[NMAX];   // dist bits | (keep1<<31)
__device__ unsigned int   g_selbits[96];
__device__ unsigned int   g_m[NB];
__device__ int            g_bucket[NB][4];
__device__ int            g_rankin[NB][4];
__device__ float          g_w[NB][4];
__device__ float          g_selval[NB][4];

// ---------------- fdlibm flt-32 atanf (branchless) / atan2f ------------------
__device__ __forceinline__ float fd_atanf(float x) {
    const float H0 = 4.6364760399e-01f, L0 = 5.0121582440e-09f;
    const float H1 = 7.8539812565e-01f, L1 = 3.7748947079e-08f;
    const float H2 = 9.8279368877e-01f, L2 = 3.4473217170e-08f;
    const float H3 = 1.5707962513e+00f, L3 = 7.5497894159e-08f;
    const float aT0 =  3.3333328366e-01f;
    const float aT1 = -1.9999158382e-01f;
    const float aT2 =  1.4253635705e-01f;
    const float aT3 = -1.0648017377e-01f;
    const float aT4 =  6.1687607318e-02f;
    unsigned bx = __float_as_uint(x);
    unsigned sign = bx >> 31;
    unsigned ix = bx & 0x7fffffffu;
    float ax = fabsf(x);
    // interval select: one division for all paths (id=-1 divides by 1.0 -> exact)
    float num, den, hi, lo;
    if (ix < 0x3ee00000u) {            // |x| < 0.4375
        num = ax; den = 1.0f; hi = 0.0f; lo = 0.0f;
    } else if (ix < 0x3f300000u) {     // < 0.6875
        num = __fsub_rn(__fadd_rn(ax, ax), 1.0f); den = __fadd_rn(2.0f, ax);
        hi = H0; lo = L0;
    } else if (ix < 0x3f980000u) {     // < 1.1875
        num = __fsub_rn(ax, 1.0f); den = __fadd_rn(ax, 1.0f);
        hi = H1; lo = L1;
    } else if (ix < 0x401c0000u) {     // < 2.4375
        num = __fsub_rn(ax, 1.5f); den = __fadd_rn(1.0f, __fmul_rn(1.5f, ax));
        hi = H2; lo = L2;
    } else {                           // >= 2.4375
        num = -1.0f; den = ax; hi = H3; lo = L3;
    }
    float xr = __fdiv_rn(num, den);
    float z = __fmul_rn(xr, xr);
    float w = __fmul_rn(z, z);
    float s1 = __fmul_rn(z, __fadd_rn(aT0, __fmul_rn(w, __fadd_rn(aT2, __fmul_rn(w, aT4)))));
    float s2 = __fmul_rn(w, __fadd_rn(aT1, __fmul_rn(w, aT3)));
    float core = __fsub_rn(hi,
        __fsub_rn(__fsub_rn(__fmul_rn(xr, __fadd_rn(s1, s2)), lo), xr));
    if (ix >= 0x4c800000u) core = H3;  // |x| >= 2^26: fdlibm returns atanhi[3]
    if (ix < 0x39800000u)  core = ax;  // |x| < 2^-12: fdlibm returns x
    return sign ? -core : core;
}

__device__ __forceinline__ float fd_atan2f(float y, float x) {
    const float pi    = 3.1415927410e+00f;
    const float pi_lo = -8.7422776573e-08f;
    const float pio2  = 1.5707963705e+00f;
    unsigned hx = __float_as_uint(x), hy = __float_as_uint(y);
    if (hx == 0x3f800000u) return fd_atanf(y);
    unsigned m = ((hy >> 31) & 1u) | ((hx >> 30) & 2u);
    unsigned ix = hx & 0x7fffffffu, iy = hy & 0x7fffffffu;
    if (iy == 0u) {
        switch (m) {
        case 0: case 1: return y;
        case 2: return pi;
        default: return -pi;
        }
    }
    if (ix == 0u) return (m & 1u) ? -pio2 : pio2;
    if (ix + (26u << 23) < iy) return (m & 1u) ? -pio2 : pio2;
    // x<0 with |y/x| < 2^-26: fdlibm uses z = atan(0)
    float ratio = fabsf(__fdiv_rn(y, x));
    if ((m & 2u) && iy + (26u << 23) < ix) ratio = 0.0f;
    float z = fd_atanf(ratio);
    // quadrant fixup via selects
    float res = z;
    if (m == 1u) res = -z;
    if (m == 2u) res = __fsub_rn(pi, __fsub_rn(z, pi_lo));
    if (m == 3u) res = __fsub_rn(__fsub_rn(z, pi_lo), pi);
    return res;
}

// ---------------- Threefry-2x32 ----------------------------------------------
__device__ __forceinline__ void tf_round(unsigned& x0, unsigned& x1, int r) {
    x0 += x1;
    x1 = __funnelshift_l(x1, x1, r);
    x1 ^= x0;
}

__device__ __forceinline__ uint2 tf2x32(unsigned k0, unsigned k1, unsigned x0, unsigned x1) {
    unsigned k2 = k0 ^ k1 ^ 0x1BD11BDAu;
    x0 += k0; x1 += k1;
    tf_round(x0, x1, 13); tf_round(x0, x1, 15); tf_round(x0, x1, 26); tf_round(x0, x1, 6);
    x0 += k1; x1 += k2 + 1u;
    tf_round(x0, x1, 17); tf_round(x0, x1, 29); tf_round(x0, x1, 16); tf_round(x0, x1, 24);
    x0 += k2; x1 += k0 + 2u;
    tf_round(x0, x1, 13); tf_round(x0, x1, 15); tf_round(x0, x1, 26); tf_round(x0, x1, 6);
    x0 += k0; x1 += k1 + 3u;
    tf_round(x0, x1, 17); tf_round(x0, x1, 29); tf_round(x0, x1, 16); tf_round(x0, x1, 24);
    x0 += k1; x1 += k2 + 4u;
    tf_round(x0, x1, 13); tf_round(x0, x1, 15); tf_round(x0, x1, 26); tf_round(x0, x1, 6);
    x0 += k2; x1 += k0 + 5u;
    return make_uint2(x0, x1);
}

__device__ __forceinline__ float bits_to_unit(unsigned bits) {
    return __fadd_rn(__uint_as_float((bits >> 9) | 0x3f800000u), -1.0f);
}

__device__ __forceinline__ unsigned warp_iscan(unsigned v, int lane) {
#pragma unroll
    for (int o = 1; o < 32; o <<= 1) {
        unsigned n = __shfl_up_sync(0xffffffffu, v, o);
        if (lane >= o) v += n;
    }
    return v;
}

__device__ __forceinline__ int div_npb(int p, unsigned long long magic) {
    return (int)(((unsigned long long)(unsigned)p * magic) >> 42);
}

// ---------------- k_init ------------------------------------------------------
__global__ void k_init() {
    if (blockIdx.x < 160) {
        uint4* p = (uint4*)&g_histall[0][0];
        unsigned base = blockIdx.x * 4096u + threadIdx.x;
#pragma unroll
        for (int i = 0; i < 4; i++)
            p[base + i * 1024u] = make_uint4(0u, 0u, 0u, 0u);
    } else {
        int t = threadIdx.x;
        if (t < 96) g_selbits[t] = 0u;
        __syncthreads();
        uint2 kg = tf2x32(0u, 42u, 0u, 0u);
        for (int i = t; i < NB * 360; i += 1024) {
            uint2 r = tf2x32(kg.x, kg.y, 0u, (unsigned)i);
            if (bits_to_unit(r.x ^ r.y) < 0.2f)
                atomicOr(&g_selbits[i >> 5], 1u << (i & 31));
        }
    }
}

// ---------------- k_stage1 -----------------------------------------------------
__global__ void k_stage1(const int4* __restrict__ coords, int N) {
    int p = blockIdx.x * blockDim.x + threadIdx.x;
    if (p >= N) return;
    int4 c = coords[p];  // (b, z, y, x)
    float xm = __fadd_rn(__fmul_rn((float)c.w, 0.1f), -70.0f);
    float ym = __fadd_rn(__fmul_rn((float)c.z, 0.1f), -40.0f);
    float th = fd_atan2f(ym, xm);
    float td = __fmul_rn(th, 57.29577951308232f);
    float tm = (td < 0.0f) ? __fadd_rn(td, 360.0f) : td;
    int grp = (int)tm;
    grp = min(max(grp, 0), 359);
    int b = c.x;
    int bitidx = b * 360 + grp;
    unsigned keep1 = (g_selbits[bitidx >> 5] >> (bitidx & 31)) & 1u;
    float d2 = __fadd_rn(__fmul_rn(xm, xm), __fmul_rn(ym, ym));
    float dist = __fsqrt_rn(d2);
    unsigned db = __float_as_uint(dist);
    if (keep1) {
        atomicAdd(&g_histall[b][db >> 16], 1u);
        db |= 0x80000000u;
    }
    g_distk[p] = db;
}

// ---------------- k_coarse -----------------------------------------------------
__global__ void k_coarse() {
    int b = blockIdx.x;
    int t = threadIdx.x, lane = t & 31, warp = t >> 5;
    const unsigned* hist = g_histall[b];
    const uint4* h4 = (const uint4*)hist;
    unsigned psum = 0;
#pragma unroll
    for (int i = 0; i < 16; i++) {
        uint4 q = h4[t * 16 + i];
        psum += q.x + q.y + q.z + q.w;
    }
    unsigned incl = warp_iscan(psum, lane);
    __shared__ unsigned wtot[32], wpre[32];
    __shared__ unsigned s_m;
    __shared__ unsigned s_r[4];
    __shared__ int      s_seg[4];
    __shared__ unsigned s_base[4];
    if (lane == 31) wtot[warp] = incl;
    __syncthreads();
    if (warp == 0) {
        unsigned v = wtot[lane];
        unsigned iv = warp_iscan(v, lane);
        wpre[lane] = iv - v;
        if (lane == 31) s_m = iv;
    }
    __syncthreads();
    unsigned m = s_m;
    if (t == 0) {
        g_m[b] = m;
        float mf  = (float)m;
        float cm1 = __fsub_rn(mf, 1.0f);
        const float qv[2] = {0.33f, 0.67f};
#pragma unroll
        for (int j = 0; j < 2; j++) {
            float qidx = __fmul_rn(qv[j], cm1);
            float lo = floorf(qidx), hi = ceilf(qidx);
            float hw = __fsub_rn(qidx, lo);
            float lw = __fsub_rn(1.0f, hw);
            float loc = fmaxf(0.0f, fminf(lo, cm1));
            float hic = fmaxf(0.0f, fminf(hi, cm1));
            s_r[j * 2]     = (unsigned)(int)loc;
            s_r[j * 2 + 1] = (unsigned)(int)hic;
            g_w[b][j * 2]     = lw;
            g_w[b][j * 2 + 1] = hw;
        }
    }
    __syncthreads();
    if (m != 0) {
        unsigned excl = wpre[warp] + incl - psum;
#pragma unroll
        for (int s = 0; s < 4; s++) {
            unsigned r = s_r[s];
            if (r >= excl && r < excl + psum) { s_seg[s] = t; s_base[s] = excl; }
        }
    }
    __syncthreads();
    if (warp < 4) {
        int s = warp;
        if (m == 0) {
            if (lane == 0) { g_bucket[b][s] = -1; g_rankin[b][s] = 0; }
        } else {
            int seg = s_seg[s];
            unsigned rrem = s_r[s] - s_base[s];
            unsigned a0 = hist[seg * 64 + 2 * lane];
            unsigned a1 = hist[seg * 64 + 2 * lane + 1];
            unsigned pr = a0 + a1;
            unsigned pincl = warp_iscan(pr, lane);
            unsigned pexcl = pincl - pr;
            if (rrem >= pexcl && rrem < pincl) {
                unsigned local = rrem - pexcl;
                int bin; unsigned rk;
                if (local < a0) { bin = seg * 64 + 2 * lane;     rk = local; }
                else            { bin = seg * 64 + 2 * lane + 1; rk = local - a0; }
                g_bucket[b][s] = bin;
                g_rankin[b][s] = (int)rk;
            }
        }
    }
}

// ---------------- k_finecnt: 4 voxels/thread, buckets cached in shared -------
__global__ void k_finecnt(int N4, unsigned long long magic) {
    __shared__ int sbuck[NB * 4];
    if (threadIdx.x < NB * 4) sbuck[threadIdx.x] = ((const int*)g_bucket)[threadIdx.x];
    __syncthreads();
    int p4 = blockIdx.x * blockDim.x + threadIdx.x;
    if (p4 >= N4) return;
    uint4 u = ((const uint4*)g_distk)[p4];
    unsigned us[4] = {u.x, u.y, u.z, u.w};
#pragma unroll
    for (int i = 0; i < 4; i++) {
        if (!(us[i] & 0x80000000u)) continue;
        unsigned bits = us[i] & 0x7fffffffu;
        int b = div_npb(p4 * 4 + i, magic);
        int coarse = (int)(bits >> 16);
        unsigned fbin = bits & 0xFFFFu;
#pragma unroll
        for (int s = 0; s < 4; s++)
            if (sbuck[b * 4 + s] == coarse)
                atomicAdd(&g_histall[8 + b * 4 + s][fbin], 1u);
    }
}

// ---------------- k_finescan ---------------------------------------------------
__global__ void k_finescan() {
    int b = blockIdx.x >> 2, s = blockIdx.x & 3;
    int bucket = g_bucket[b][s];
    int t = threadIdx.x, lane = t & 31, warp = t >> 5;
    if (bucket < 0) {
        if (t == 0) g_selval[b][s] = __int_as_float(0x7fc00000);
        return;
    }
    const unsigned* hist = g_histall[8 + b * 4 + s];
    const uint4* h4 = (const uint4*)hist;
    unsigned psum = 0;
#pragma unroll
    for (int i = 0; i < 16; i++) {
        uint4 q = h4[t * 16 + i];
        psum += q.x + q.y + q.z + q.w;
    }
    unsigned incl = warp_iscan(psum, lane);
    __shared__ unsigned wtot[32], wpre[32];
    __shared__ int      s_seg;
    __shared__ unsigned s_base;
    if (lane == 31) wtot[warp] = incl;
    __syncthreads();
    if (warp == 0) {
        unsigned v = wtot[lane];
        unsigned iv = warp_iscan(v, lane);
        wpre[lane] = iv - v;
    }
    __syncthreads();
    unsigned r = (unsigned)g_rankin[b][s];
    unsigned excl = wpre[warp] + incl - psum;
    if (r >= excl && r < excl + psum) { s_seg = t; s_base = excl; }
    __syncthreads();
    if (warp == 0) {
        int seg = s_seg;
        unsigned rrem = r - s_base;
        unsigned a0 = hist[seg * 64 + 2 * lane];
        unsigned a1 = hist[seg * 64 + 2 * lane + 1];
        unsigned pr = a0 + a1;
        unsigned pincl = warp_iscan(pr, lane);
        unsigned pexcl = pincl - pr;
        if (rrem >= pexcl && rrem < pincl) {
            unsigned local = rrem - pexcl;
            int bin = (local < a0) ? (seg * 64 + 2 * lane) : (seg * 64 + 2 * lane + 1);
            g_selval[b][s] = __uint_as_float(((unsigned)bucket << 16) | (unsigned)bin);
        }
    }
}

// ---------------- k_final: fused keep + copy ----------------------------------
__global__ void k_final(const float4* __restrict__ feat, float* __restrict__ out_keep,
                        float4* __restrict__ out_feat, int N, unsigned long long magic) {
    __shared__ unsigned s_keep;
    int t = threadIdx.x;
    int vbase = blockIdx.x * 32;
    if (t < 32) {
        int p = vbase + t;
        bool keep = false;
        if (p < N) {
            unsigned u = g_distk[p];
            float dist = __uint_as_float(u & 0x7fffffffu);
            int b = div_npb(p, magic);
            float q1, q2;
            if (g_m[b] == 0) {
                q1 = q2 = __int_as_float(0x7fc00000);
            } else {
                q1 = __fadd_rn(__fmul_rn(g_selval[b][0], g_w[b][0]),
                               __fmul_rn(g_selval[b][1], g_w[b][1]));
                q2 = __fadd_rn(__fmul_rn(g_selval[b][2], g_w[b][2]),
                               __fmul_rn(g_selval[b][3], g_w[b][3]));
            }
            float prob = (dist < q1) ? 0.48f : ((dist < q2) ? 0.8f : 0.95f);
            uint2 kv = tf2x32(0u, 42u, 0u, 1u);
            uint2 r = tf2x32(kv.x, kv.y, 0u, (unsigned)p);
            float uu = bits_to_unit(r.x ^ r.y);
            keep = (u >> 31) && (uu >= prob);
            if (out_keep != nullptr) out_keep[p] = keep ? 1.0f : 0.0f;
        }
        unsigned bal = __ballot_sync(0xffffffffu, keep);
        if (t == 0) s_keep = bal;
    }
    __syncthreads();
    if (out_feat == nullptr) return;
    int vloc = t >> 4;
    int v = vbase + vloc;
    if (v >= N) return;
    int lane16 = t & 15;
    size_t off = (size_t)v * 16 + lane16;
    if ((s_keep >> vloc) & 1u) {
        __stcs(&out_feat[off], __ldcs(&feat[off]));
    } else {
        __stcs(&out_feat[off], make_float4(0.0f, 0.0f, 0.0f, 0.0f));
    }
}

// ---------------- launcher -------------------------------------------------------
extern "C" void kernel_launch(void* const* d_in, const int* in_sizes, int n_in,
                              void* d_out, int out_size) {
    int i_coords = 0, i_feat = 1;
    if (n_in >= 2 && in_sizes[0] > in_sizes[1]) { i_coords = 1; i_feat = 0; }
    const int4*   coords = (const int4*)d_in[i_coords];
    const float4* feat   = (const float4*)d_in[i_feat];
    int N = in_sizes[i_coords] / 4;
    int npb = N / NB;
    unsigned long long magic = (4398046511104ULL / (unsigned long long)npb) + 1ULL;
    int N4 = N / 4;

    float*  out      = (float*)d_out;
    float*  out_keep = nullptr;
    float4* out_feat = nullptr;
    long long os = (long long)out_size;
    if (os >= (long long)N * 65) {
        out_keep = out;
        out_feat = (float4*)(out + N);
    } else if (os >= (long long)N * 64) {
        out_feat = (float4*)out;
    } else {
        out_keep = out;
    }

    int nb  = (N + 255) / 256;
    int nb4 = (N4 + 255) / 256;
    k_init<<<161, 1024>>>();
    k_stage1<<<nb, 256>>>(coords, N);
    k_coarse<<<NB, 1024>>>();
    k_finecnt<<<nb4, 256>>>(N4, magic);
    k_finescan<<<NB * 4, 1024>>>();
    k_final<<<(N + 31) / 32, 512>>>(feat, out_keep, out_feat, N, magic);
}

// round 11
// speedup vs baseline: 1.1915x; 1.1017x over previous
#include <cuda_runtime.h>
#include <stdint.h>
#include <math.h>

// ============================================================================
// RadialMasking — bit-exact JAX reproduction (fdlibm atan2f, confirmed R4).
//  R11 perf: k_final processes 256 voxels/block (phase1 = 8 warps in parallel,
//  8x copy loop) to kill wave-synchronized phase-1 latency bubbles;
//  k_init slimmed (fine hists zeroed inside k_coarse instead).
// ============================================================================

#define NMAX 1600000
#define NB 8
#define VPB 256   // voxels per k_final block

__device__ unsigned int   g_histall[8 + NB * 4][65536];
__device__ __align__(16) unsigned int g_distk[NMAX];   // dist bits | (keep1<<31)
__device__ unsigned int   g_selbits[96];
__device__ unsigned int   g_m[NB];
__device__ int            g_bucket[NB][4];
__device__ int            g_rankin[NB][4];
__device__ float          g_w[NB][4];
__device__ float          g_selval[NB][4];

// ---------------- fdlibm flt-32 atanf (branchless) / atan2f ------------------
__device__ __forceinline__ float fd_atanf(float x) {
    const float H0 = 4.6364760399e-01f, L0 = 5.0121582440e-09f;
    const float H1 = 7.8539812565e-01f, L1 = 3.7748947079e-08f;
    const float H2 = 9.8279368877e-01f, L2 = 3.4473217170e-08f;
    const float H3 = 1.5707962513e+00f, L3 = 7.5497894159e-08f;
    const float aT0 =  3.3333328366e-01f;
    const float aT1 = -1.9999158382e-01f;
    const float aT2 =  1.4253635705e-01f;
    const float aT3 = -1.0648017377e-01f;
    const float aT4 =  6.1687607318e-02f;
    unsigned bx = __float_as_uint(x);
    unsigned sign = bx >> 31;
    unsigned ix = bx & 0x7fffffffu;
    float ax = fabsf(x);
    float num, den, hi, lo;
    if (ix < 0x3ee00000u) {            // |x| < 0.4375
        num = ax; den = 1.0f; hi = 0.0f; lo = 0.0f;
    } else if (ix < 0x3f300000u) {     // < 0.6875
        num = __fsub_rn(__fadd_rn(ax, ax), 1.0f); den = __fadd_rn(2.0f, ax);
        hi = H0; lo = L0;
    } else if (ix < 0x3f980000u) {     // < 1.1875
        num = __fsub_rn(ax, 1.0f); den = __fadd_rn(ax, 1.0f);
        hi = H1; lo = L1;
    } else if (ix < 0x401c0000u) {     // < 2.4375
        num = __fsub_rn(ax, 1.5f); den = __fadd_rn(1.0f, __fmul_rn(1.5f, ax));
        hi = H2; lo = L2;
    } else {                           // >= 2.4375
        num = -1.0f; den = ax; hi = H3; lo = L3;
    }
    float xr = __fdiv_rn(num, den);
    float z = __fmul_rn(xr, xr);
    float w = __fmul_rn(z, z);
    float s1 = __fmul_rn(z, __fadd_rn(aT0, __fmul_rn(w, __fadd_rn(aT2, __fmul_rn(w, aT4)))));
    float s2 = __fmul_rn(w, __fadd_rn(aT1, __fmul_rn(w, aT3)));
    float core = __fsub_rn(hi,
        __fsub_rn(__fsub_rn(__fmul_rn(xr, __fadd_rn(s1, s2)), lo), xr));
    if (ix >= 0x4c800000u) core = H3;
    if (ix < 0x39800000u)  core = ax;
    return sign ? -core : core;
}

__device__ __forceinline__ float fd_atan2f(float y, float x) {
    const float pi    = 3.1415927410e+00f;
    const float pi_lo = -8.7422776573e-08f;
    const float pio2  = 1.5707963705e+00f;
    unsigned hx = __float_as_uint(x), hy = __float_as_uint(y);
    if (hx == 0x3f800000u) return fd_atanf(y);
    unsigned m = ((hy >> 31) & 1u) | ((hx >> 30) & 2u);
    unsigned ix = hx & 0x7fffffffu, iy = hy & 0x7fffffffu;
    if (iy == 0u) {
        switch (m) {
        case 0: case 1: return y;
        case 2: return pi;
        default: return -pi;
        }
    }
    if (ix == 0u) return (m & 1u) ? -pio2 : pio2;
    if (ix + (26u << 23) < iy) return (m & 1u) ? -pio2 : pio2;
    float ratio = fabsf(__fdiv_rn(y, x));
    if ((m & 2u) && iy + (26u << 23) < ix) ratio = 0.0f;
    float z = fd_atanf(ratio);
    float res = z;
    if (m == 1u) res = -z;
    if (m == 2u) res = __fsub_rn(pi, __fsub_rn(z, pi_lo));
    if (m == 3u) res = __fsub_rn(__fsub_rn(z, pi_lo), pi);
    return res;
}

// ---------------- Threefry-2x32 ----------------------------------------------
__device__ __forceinline__ void tf_round(unsigned& x0, unsigned& x1, int r) {
    x0 += x1;
    x1 = __funnelshift_l(x1, x1, r);
    x1 ^= x0;
}

__device__ __forceinline__ uint2 tf2x32(unsigned k0, unsigned k1, unsigned x0, unsigned x1) {
    unsigned k2 = k0 ^ k1 ^ 0x1BD11BDAu;
    x0 += k0; x1 += k1;
    tf_round(x0, x1, 13); tf_round(x0, x1, 15); tf_round(x0, x1, 26); tf_round(x0, x1, 6);
    x0 += k1; x1 += k2 + 1u;
    tf_round(x0, x1, 17); tf_round(x0, x1, 29); tf_round(x0, x1, 16); tf_round(x0, x1, 24);
    x0 += k2; x1 += k0 + 2u;
    tf_round(x0, x1, 13); tf_round(x0, x1, 15); tf_round(x0, x1, 26); tf_round(x0, x1, 6);
    x0 += k0; x1 += k1 + 3u;
    tf_round(x0, x1, 17); tf_round(x0, x1, 29); tf_round(x0, x1, 16); tf_round(x0, x1, 24);
    x0 += k1; x1 += k2 + 4u;
    tf_round(x0, x1, 13); tf_round(x0, x1, 15); tf_round(x0, x1, 26); tf_round(x0, x1, 6);
    x0 += k2; x1 += k0 + 5u;
    return make_uint2(x0, x1);
}

__device__ __forceinline__ float bits_to_unit(unsigned bits) {
    return __fadd_rn(__uint_as_float((bits >> 9) | 0x3f800000u), -1.0f);
}

__device__ __forceinline__ unsigned warp_iscan(unsigned v, int lane) {
#pragma unroll
    for (int o = 1; o < 32; o <<= 1) {
        unsigned n = __shfl_up_sync(0xffffffffu, v, o);
        if (lane >= o) v += n;
    }
    return v;
}

__device__ __forceinline__ int div_npb(int p, unsigned long long magic) {
    return (int)(((unsigned long long)(unsigned)p * magic) >> 42);
}

// ---------------- k_init: zero coarse hists + selgroups ----------------------
__global__ void k_init() {
    if (blockIdx.x < 32) {
        uint4* p = (uint4*)&g_histall[0][0];     // coarse region: 8*65536 u32
        unsigned base = blockIdx.x * 4096u + threadIdx.x;
#pragma unroll
        for (int i = 0; i < 4; i++)
            p[base + i * 1024u] = make_uint4(0u, 0u, 0u, 0u);
    } else {
        int t = threadIdx.x;
        if (t < 96) g_selbits[t] = 0u;
        __syncthreads();
        uint2 kg = tf2x32(0u, 42u, 0u, 0u);
        for (int i = t; i < NB * 360; i += 1024) {
            uint2 r = tf2x32(kg.x, kg.y, 0u, (unsigned)i);
            if (bits_to_unit(r.x ^ r.y) < 0.2f)
                atomicOr(&g_selbits[i >> 5], 1u << (i & 31));
        }
    }
}

// ---------------- k_stage1 -----------------------------------------------------
__global__ void k_stage1(const int4* __restrict__ coords, int N) {
    int p = blockIdx.x * blockDim.x + threadIdx.x;
    if (p >= N) return;
    int4 c = coords[p];  // (b, z, y, x)
    float xm = __fadd_rn(__fmul_rn((float)c.w, 0.1f), -70.0f);
    float ym = __fadd_rn(__fmul_rn((float)c.z, 0.1f), -40.0f);
    float th = fd_atan2f(ym, xm);
    float td = __fmul_rn(th, 57.29577951308232f);
    float tm = (td < 0.0f) ? __fadd_rn(td, 360.0f) : td;
    int grp = (int)tm;
    grp = min(max(grp, 0), 359);
    int b = c.x;
    int bitidx = b * 360 + grp;
    unsigned keep1 = (g_selbits[bitidx >> 5] >> (bitidx & 31)) & 1u;
    float d2 = __fadd_rn(__fmul_rn(xm, xm), __fmul_rn(ym, ym));
    float dist = __fsqrt_rn(d2);
    unsigned db = __float_as_uint(dist);
    if (keep1) {
        atomicAdd(&g_histall[b][db >> 16], 1u);
        db |= 0x80000000u;
    }
    g_distk[p] = db;
}

// ---------------- k_coarse (also zeroes this batch's fine hists) -------------
__global__ void k_coarse() {
    int b = blockIdx.x;
    int t = threadIdx.x, lane = t & 31, warp = t >> 5;
    // zero fine hists for batch b: 4 * 65536 u32 = 65536 uint4
    {
        uint4* fz = (uint4*)&g_histall[8 + b * 4][0];
#pragma unroll
        for (int i = 0; i < 64; i++)
            fz[t + i * 1024] = make_uint4(0u, 0u, 0u, 0u);
    }
    const unsigned* hist = g_histall[b];
    const uint4* h4 = (const uint4*)hist;
    unsigned psum = 0;
#pragma unroll
    for (int i = 0; i < 16; i++) {
        uint4 q = h4[t * 16 + i];
        psum += q.x + q.y + q.z + q.w;
    }
    unsigned incl = warp_iscan(psum, lane);
    __shared__ unsigned wtot[32], wpre[32];
    __shared__ unsigned s_m;
    __shared__ unsigned s_r[4];
    __shared__ int      s_seg[4];
    __shared__ unsigned s_base[4];
    if (lane == 31) wtot[warp] = incl;
    __syncthreads();
    if (warp == 0) {
        unsigned v = wtot[lane];
        unsigned iv = warp_iscan(v, lane);
        wpre[lane] = iv - v;
        if (lane == 31) s_m = iv;
    }
    __syncthreads();
    unsigned m = s_m;
    if (t == 0) {
        g_m[b] = m;
        float mf  = (float)m;
        float cm1 = __fsub_rn(mf, 1.0f);
        const float qv[2] = {0.33f, 0.67f};
#pragma unroll
        for (int j = 0; j < 2; j++) {
            float qidx = __fmul_rn(qv[j], cm1);
            float lo = floorf(qidx), hi = ceilf(qidx);
            float hw = __fsub_rn(qidx, lo);
            float lw = __fsub_rn(1.0f, hw);
            float loc = fmaxf(0.0f, fminf(lo, cm1));
            float hic = fmaxf(0.0f, fminf(hi, cm1));
            s_r[j * 2]     = (unsigned)(int)loc;
            s_r[j * 2 + 1] = (unsigned)(int)hic;
            g_w[b][j * 2]     = lw;
            g_w[b][j * 2 + 1] = hw;
        }
    }
    __syncthreads();
    if (m != 0) {
        unsigned excl = wpre[warp] + incl - psum;
#pragma unroll
        for (int s = 0; s < 4; s++) {
            unsigned r = s_r[s];
            if (r >= excl && r < excl + psum) { s_seg[s] = t; s_base[s] = excl; }
        }
    }
    __syncthreads();
    if (warp < 4) {
        int s = warp;
        if (m == 0) {
            if (lane == 0) { g_bucket[b][s] = -1; g_rankin[b][s] = 0; }
        } else {
            int seg = s_seg[s];
            unsigned rrem = s_r[s] - s_base[s];
            unsigned a0 = hist[seg * 64 + 2 * lane];
            unsigned a1 = hist[seg * 64 + 2 * lane + 1];
            unsigned pr = a0 + a1;
            unsigned pincl = warp_iscan(pr, lane);
            unsigned pexcl = pincl - pr;
            if (rrem >= pexcl && rrem < pincl) {
                unsigned local = rrem - pexcl;
                int bin; unsigned rk;
                if (local < a0) { bin = seg * 64 + 2 * lane;     rk = local; }
                else            { bin = seg * 64 + 2 * lane + 1; rk = local - a0; }
                g_bucket[b][s] = bin;
                g_rankin[b][s] = (int)rk;
            }
        }
    }
}

// ---------------- k_finecnt: 4 voxels/thread, buckets cached in shared -------
__global__ void k_finecnt(int N4, unsigned long long magic) {
    __shared__ int sbuck[NB * 4];
    if (threadIdx.x < NB * 4) sbuck[threadIdx.x] = ((const int*)g_bucket)[threadIdx.x];
    __syncthreads();
    int p4 = blockIdx.x * blockDim.x + threadIdx.x;
    if (p4 >= N4) return;
    uint4 u = ((const uint4*)g_distk)[p4];
    unsigned us[4] = {u.x, u.y, u.z, u.w};
#pragma unroll
    for (int i = 0; i < 4; i++) {
        if (!(us[i] & 0x80000000u)) continue;
        unsigned bits = us[i] & 0x7fffffffu;
        int b = div_npb(p4 * 4 + i, magic);
        int coarse = (int)(bits >> 16);
        unsigned fbin = bits & 0xFFFFu;
#pragma unroll
        for (int s = 0; s < 4; s++)
            if (sbuck[b * 4 + s] == coarse)
                atomicAdd(&g_histall[8 + b * 4 + s][fbin], 1u);
    }
}

// ---------------- k_finescan ---------------------------------------------------
__global__ void k_finescan() {
    int b = blockIdx.x >> 2, s = blockIdx.x & 3;
    int bucket = g_bucket[b][s];
    int t = threadIdx.x, lane = t & 31, warp = t >> 5;
    if (bucket < 0) {
        if (t == 0) g_selval[b][s] = __int_as_float(0x7fc00000);
        return;
    }
    const unsigned* hist = g_histall[8 + b * 4 + s];
    const uint4* h4 = (const uint4*)hist;
    unsigned psum = 0;
#pragma unroll
    for (int i = 0; i < 16; i++) {
        uint4 q = h4[t * 16 + i];
        psum += q.x + q.y + q.z + q.w;
    }
    unsigned incl = warp_iscan(psum, lane);
    __shared__ unsigned wtot[32], wpre[32];
    __shared__ int      s_seg;
    __shared__ unsigned s_base;
    if (lane == 31) wtot[warp] = incl;
    __syncthreads();
    if (warp == 0) {
        unsigned v = wtot[lane];
        unsigned iv = warp_iscan(v, lane);
        wpre[lane] = iv - v;
    }
    __syncthreads();
    unsigned r = (unsigned)g_rankin[b][s];
    unsigned excl = wpre[warp] + incl - psum;
    if (r >= excl && r < excl + psum) { s_seg = t; s_base = excl; }
    __syncthreads();
    if (warp == 0) {
        int seg = s_seg;
        unsigned rrem = r - s_base;
        unsigned a0 = hist[seg * 64 + 2 * lane];
        unsigned a1 = hist[seg * 64 + 2 * lane + 1];
        unsigned pr = a0 + a1;
        unsigned pincl = warp_iscan(pr, lane);
        unsigned pexcl = pincl - pr;
        if (rrem >= pexcl && rrem < pincl) {
            unsigned local = rrem - pexcl;
            int bin = (local < a0) ? (seg * 64 + 2 * lane) : (seg * 64 + 2 * lane + 1);
            g_selval[b][s] = __uint_as_float(((unsigned)bucket << 16) | (unsigned)bin);
        }
    }
}

// ---------------- k_final: fused keep + copy, 256 voxels/block ----------------
// Phase 1: threads 0..255 (8 warps) compute keep for the block's 256 voxels,
// write out_keep, publish 8 ballot words to shared. Phase 2: all 512 threads
// loop 8x over the 4096 copy lane-tasks (16 lanes per voxel, coalesced 512B).
__global__ void __launch_bounds__(512) k_final(
        const float4* __restrict__ feat, float* __restrict__ out_keep,
        float4* __restrict__ out_feat, int N, unsigned long long magic) {
    __shared__ unsigned s_keep[VPB / 32];
    int t = threadIdx.x;
    int vbase = blockIdx.x * VPB;
    if (t < VPB) {
        int p = vbase + t;
        bool keep = false;
        if (p < N) {
            unsigned u = g_distk[p];
            float dist = __uint_as_float(u & 0x7fffffffu);
            int b = div_npb(p, magic);
            float q1, q2;
            if (g_m[b] == 0) {
                q1 = q2 = __int_as_float(0x7fc00000);
            } else {
                q1 = __fadd_rn(__fmul_rn(g_selval[b][0], g_w[b][0]),
                               __fmul_rn(g_selval[b][1], g_w[b][1]));
                q2 = __fadd_rn(__fmul_rn(g_selval[b][2], g_w[b][2]),
                               __fmul_rn(g_selval[b][3], g_w[b][3]));
            }
            float prob = (dist < q1) ? 0.48f : ((dist < q2) ? 0.8f : 0.95f);
            uint2 kv = tf2x32(0u, 42u, 0u, 1u);   // compile-time constant
            uint2 r = tf2x32(kv.x, kv.y, 0u, (unsigned)p);
            float uu = bits_to_unit(r.x ^ r.y);
            keep = (u >> 31) && (uu >= prob);
            if (out_keep != nullptr) out_keep[p] = keep ? 1.0f : 0.0f;
        }
        unsigned bal = __ballot_sync(0xffffffffu, keep);
        if ((t & 31) == 0) s_keep[t >> 5] = bal;
    }
    __syncthreads();
    if (out_feat == nullptr) return;
    const float4 z4 = make_float4(0.0f, 0.0f, 0.0f, 0.0f);
#pragma unroll
    for (int i = 0; i < VPB * 16 / 512; i++) {
        int task = i * 512 + t;
        int vloc = task >> 4;
        int v = vbase + vloc;
        if (v >= N) return;
        int lane16 = task & 15;
        size_t off = (size_t)v * 16 + lane16;
        if ((s_keep[vloc >> 5] >> (vloc & 31)) & 1u) {
            __stcs(&out_feat[off], __ldcs(&feat[off]));
        } else {
            __stcs(&out_feat[off], z4);
        }
    }
}

// ---------------- launcher -------------------------------------------------------
extern "C" void kernel_launch(void* const* d_in, const int* in_sizes, int n_in,
                              void* d_out, int out_size) {
    int i_coords = 0, i_feat = 1;
    if (n_in >= 2 && in_sizes[0] > in_sizes[1]) { i_coords = 1; i_feat = 0; }
    const int4*   coords = (const int4*)d_in[i_coords];
    const float4* feat   = (const float4*)d_in[i_feat];
    int N = in_sizes[i_coords] / 4;
    int npb = N / NB;
    unsigned long long magic = (4398046511104ULL / (unsigned long long)npb) + 1ULL;
    int N4 = N / 4;

    float*  out      = (float*)d_out;
    float*  out_keep = nullptr;
    float4* out_feat = nullptr;
    long long os = (long long)out_size;
    if (os >= (long long)N * 65) {
        out_keep = out;
        out_feat = (float4*)(out + N);
    } else if (os >= (long long)N * 64) {
        out_feat = (float4*)out;
    } else {
        out_keep = out;
    }

    int nb  = (N + 255) / 256;
    int nb4 = (N4 + 255) / 256;
    k_init<<<33, 1024>>>();
    k_stage1<<<nb, 256>>>(coords, N);
    k_coarse<<<NB, 1024>>>();
    k_finecnt<<<nb4, 256>>>(N4, magic);
    k_finescan<<<NB * 4, 1024>>>();
    k_final<<<(N + VPB - 1) / VPB, 512>>>(feat, out_keep, out_feat, N, magic);
}